// round 6
// baseline (speedup 1.0000x reference)
#include <cuda_runtime.h>

#define BB 4096
#define SS 32
#define TT 32
#define VOC 256
#define EE 128
#define HH 64
#define AA 64
#define GH3 192   /* 3*H */

// ---------------- scratch (device globals; no allocation allowed) ----------------
__device__ float g_fwd[BB * SS * HH];      // forward encoder states
__device__ float g_bwd[BB * SS * HH];      // backward encoder states
__device__ float g_enc[BB * SS * HH];      // encoded = fwd + bwd
__device__ float g_encproj[BB * SS * AA];  // encoded @ attn_We + be
__device__ float g_hid[BB * TT * HH];      // decoder hidden states

// ---------------- fast, accurate-enough activations ----------------
__device__ __forceinline__ float fsigmoid(float x) {
    return __fdividef(1.0f, 1.0f + __expf(-x));
}
__device__ __forceinline__ float ftanh(float x) {
    // tanh(x) = 1 - 2/(e^{2x}+1); saturates correctly at +/-inf, branch-free
    float e = __expf(2.0f * x);
    return 1.0f - __fdividef(2.0f, e + 1.0f);
}

// =================================================================
// Encoder: both directions in one launch (blockIdx.y = dir).
// G=8 batch elements per block, 192 threads; thread j owns gate
// column j for all 8 elements.
// =================================================================
__global__ __launch_bounds__(192)
void enc_kernel(const int* __restrict__ src_ids,
                const float* __restrict__ src_emb,
                const float* __restrict__ Wf, const float* __restrict__ Uf,
                const float* __restrict__ bf,
                const float* __restrict__ Wb, const float* __restrict__ Ub,
                const float* __restrict__ bb)
{
    constexpr int G = 8;
    const bool BWD = (blockIdx.y != 0);
    const float* W    = BWD ? Wb : Wf;
    const float* U    = BWD ? Ub : Uf;
    const float* bias = BWD ? bb : bf;
    float* dst        = BWD ? g_bwd : g_fwd;

    extern __shared__ float sm[];
    float* sW  = sm;                 // 128*192
    float* sU  = sW + EE * GH3;      // 64*192
    float* sB  = sU + HH * GH3;      // 384
    float* sX  = sB + 2 * GH3;       // G*128
    float* sXP = sX + G * EE;        // G*192
    float* sHP = sXP + G * GH3;      // G*192
    float* sH  = sHP + G * GH3;      // G*64

    const int tid = threadIdx.x;
    for (int i = tid; i < EE * GH3; i += 192) sW[i] = W[i];
    for (int i = tid; i < HH * GH3; i += 192) sU[i] = U[i];
    for (int i = tid; i < 2 * GH3; i += 192) sB[i] = bias[i];
    for (int i = tid; i < G * HH; i += 192) sH[i] = 0.0f;

    const int b0 = blockIdx.x * G;
    __syncthreads();

    for (int step = 0; step < SS; ++step) {
        const int s = BWD ? (SS - 1 - step) : step;

        // stage embeddings for the 8 batch elements
        for (int i = tid; i < G * EE; i += 192) {
            int g = i >> 7;
            int k = i & 127;
            int id = src_ids[(b0 + g) * SS + s];
            sX[i] = src_emb[id * EE + k];
        }
        __syncthreads();

        const int j = tid;  // gate column 0..191
        float xp[G], hp[G];
        #pragma unroll
        for (int g = 0; g < G; ++g) { xp[g] = sB[j]; hp[g] = sB[GH3 + j]; }

        #pragma unroll 4
        for (int kc = 0; kc < EE / 4; ++kc) {
            float4 xv[G];
            #pragma unroll
            for (int g = 0; g < G; ++g) xv[g] = *(const float4*)&sX[g * EE + kc * 4];
            #pragma unroll
            for (int q = 0; q < 4; ++q) {
                float w = sW[(kc * 4 + q) * GH3 + j];
                #pragma unroll
                for (int g = 0; g < G; ++g) {
                    float xk = (q == 0) ? xv[g].x : (q == 1) ? xv[g].y : (q == 2) ? xv[g].z : xv[g].w;
                    xp[g] += w * xk;
                }
            }
        }
        #pragma unroll 4
        for (int kc = 0; kc < HH / 4; ++kc) {
            float4 hv[G];
            #pragma unroll
            for (int g = 0; g < G; ++g) hv[g] = *(const float4*)&sH[g * HH + kc * 4];
            #pragma unroll
            for (int q = 0; q < 4; ++q) {
                float u = sU[(kc * 4 + q) * GH3 + j];
                #pragma unroll
                for (int g = 0; g < G; ++g) {
                    float hk = (q == 0) ? hv[g].x : (q == 1) ? hv[g].y : (q == 2) ? hv[g].z : hv[g].w;
                    hp[g] += u * hk;
                }
            }
        }
        #pragma unroll
        for (int g = 0; g < G; ++g) { sXP[g * GH3 + j] = xp[g]; sHP[g * GH3 + j] = hp[g]; }
        __syncthreads();

        // gates (512 tasks over 192 threads)
        for (int idx = tid; idx < G * HH; idx += 192) {
            int g  = idx >> 6;
            int jj = idx & 63;
            const float* XP = &sXP[g * GH3];
            const float* HP = &sHP[g * GH3];
            float z = fsigmoid(XP[jj] + HP[jj]);
            float r = fsigmoid(XP[HH + jj] + HP[HH + jj]);
            float n = ftanh(XP[2 * HH + jj] + r * HP[2 * HH + jj]);
            float hold = sH[g * HH + jj];
            float hn = z * hold + (1.0f - z) * n;
            sH[g * HH + jj] = hn;
            dst[(b0 + g) * SS * HH + s * HH + jj] = hn;
        }
        __syncthreads();
    }
}

// =================================================================
// encoded = fwd + bwd (fused); enc_proj = encoded @ attn_We + be
// rows = B*S
// =================================================================
__global__ __launch_bounds__(256)
void proj_kernel(const float* __restrict__ We, const float* __restrict__ be)
{
    extern __shared__ float sm[];
    float* sWe = sm;              // 64*64
    float* sbe = sWe + HH * AA;   // 64
    float* sR  = sbe + 64;        // 64 rows * 64

    const int tid = threadIdx.x;
    for (int i = tid; i < HH * AA; i += 256) sWe[i] = We[i];
    if (tid < 64) sbe[tid] = be[tid];
    const int rbase = blockIdx.x * 64;
    for (int i = tid; i < 64 * HH; i += 256) {
        float e = g_fwd[rbase * HH + i] + g_bwd[rbase * HH + i];
        sR[i] = e;
        g_enc[rbase * HH + i] = e;
    }
    __syncthreads();

    const int a  = tid & 63;
    const int rq = tid >> 6;  // 0..3 -> 16 rows each
    float acc[16];
    #pragma unroll
    for (int r = 0; r < 16; ++r) acc[r] = sbe[a];
    for (int k = 0; k < HH; ++k) {
        float w = sWe[k * AA + a];
        #pragma unroll
        for (int r = 0; r < 16; ++r) acc[r] += w * sR[(rq * 16 + r) * HH + k];
    }
    #pragma unroll
    for (int r = 0; r < 16; ++r)
        g_encproj[(rbase + rq * 16 + r) * AA + a] = acc[r];
}

// =================================================================
// Decoder: Bahdanau attention + GRU. G=4 batch/block, 192 threads.
// enc_proj cached in smem with 65-float row pitch (bank-conflict free).
// =================================================================
__global__ __launch_bounds__(192)
void dec_kernel(const int* __restrict__ tgt_ids,
                const float* __restrict__ dW, const float* __restrict__ dU,
                const float* __restrict__ db,
                const float* __restrict__ Wd, const float* __restrict__ bd,
                const float* __restrict__ av, const float* __restrict__ bv,
                const float* __restrict__ outW)
{
    constexpr int G = 4;
    constexpr int EPL = AA + 1;  // 65: padded pitch
    extern __shared__ float sm[];
    float* sW  = sm;                  // 128*192
    float* sU  = sW + 128 * GH3;      // 64*192
    float* sB  = sU + HH * GH3;       // 384
    float* sWd = sB + 2 * GH3;        // 64*64
    float* sbd = sWd + HH * AA;       // 64
    float* sv  = sbd + AA;            // 64
    float* sEP = sv + AA;             // G*32*65
    float* sIn = sEP + G * SS * EPL;  // G*128
    float* sXP = sIn + G * 128;       // G*192
    float* sHP = sXP + G * GH3;       // G*192
    float* sH  = sHP + G * GH3;       // G*64
    float* sDP = sH + G * HH;         // G*64
    float* sLg = sDP + G * AA;        // G*32
    float* sInv = sLg + G * SS;       // G

    const int tid = threadIdx.x;
    const int b0 = blockIdx.x * G;

    for (int i = tid; i < 128 * GH3; i += 192) sW[i] = dW[i];
    for (int i = tid; i < HH * GH3; i += 192) sU[i] = dU[i];
    for (int i = tid; i < 2 * GH3; i += 192) sB[i] = db[i];
    for (int i = tid; i < HH * AA; i += 192) sWd[i] = Wd[i];
    if (tid < AA) { sbd[tid] = bd[tid]; sv[tid] = av[tid]; }
    const float bvv = bv[0];

    for (int i = tid; i < G * SS * AA; i += 192) {
        int g = i / (SS * AA);
        int rem = i - g * SS * AA;
        int s = rem >> 6;
        int a = rem & 63;
        sEP[g * SS * EPL + s * EPL + a] = g_encproj[(b0 + g) * SS * AA + rem];
    }
    // h0 = encoded[:, 0]
    for (int i = tid; i < G * HH; i += 192) {
        int g = i >> 6; int jj = i & 63;
        sH[i] = g_enc[(b0 + g) * SS * HH + jj];
    }
    __syncthreads();

    for (int t = 0; t < TT; ++t) {
        // dproj = h @ Wd + bd; also stage tied-embedding x into sIn[:, 0:64]
        for (int idx = tid; idx < G * AA; idx += 192) {
            int g = idx >> 6; int a = idx & 63;
            float acc = sbd[a];
            #pragma unroll 8
            for (int h = 0; h < HH; ++h) acc += sH[g * HH + h] * sWd[h * AA + a];
            sDP[g * AA + a] = acc;
            int id = (t == 0) ? 1 : tgt_ids[(b0 + g) * TT + (t - 1)];
            sIn[g * 128 + a] = __ldg(&outW[a * VOC + id]) * 8.0f;  // tied table * sqrt(H)
        }
        __syncthreads();

        // attention scores
        for (int idx = tid; idx < G * SS; idx += 192) {
            int g = idx >> 5; int s = idx & 31;
            const float* ep = &sEP[g * SS * EPL + s * EPL];
            const float* dp = &sDP[g * AA];
            float acc = bvv;
            #pragma unroll 8
            for (int a = 0; a < AA; ++a) acc += sv[a] * ftanh(dp[a] + ep[a]);
            sLg[g * SS + s] = acc;
        }
        __syncthreads();

        // softmax over S (one thread per batch element)
        if (tid < G) {
            int g = tid;
            float m = -1e30f;
            for (int s = 0; s < SS; ++s) m = fmaxf(m, sLg[g * SS + s]);
            float sum = 0.0f;
            for (int s = 0; s < SS; ++s) {
                float e = __expf(sLg[g * SS + s] - m);
                sLg[g * SS + s] = e;
                sum += e;
            }
            sInv[g] = __fdividef(1.0f, sum);
        }
        __syncthreads();

        // context -> sIn[:, 64:128]
        for (int idx = tid; idx < G * HH; idx += 192) {
            int g = idx >> 6; int h = idx & 63;
            const float* encb = &g_enc[(b0 + g) * SS * HH];
            float acc = 0.0f;
            #pragma unroll
            for (int s = 0; s < SS; ++s) acc += sLg[g * SS + s] * __ldg(&encb[s * HH + h]);
            sIn[g * 128 + HH + h] = acc * sInv[g];
        }
        __syncthreads();

        // GRU: xp = att_in @ dec_W + b0 ; hp = h @ dec_U + b1
        const int j = tid;
        float xp[G], hp[G];
        #pragma unroll
        for (int g = 0; g < G; ++g) { xp[g] = sB[j]; hp[g] = sB[GH3 + j]; }

        #pragma unroll 4
        for (int kc = 0; kc < 128 / 4; ++kc) {
            float4 xv[G];
            #pragma unroll
            for (int g = 0; g < G; ++g) xv[g] = *(const float4*)&sIn[g * 128 + kc * 4];
            #pragma unroll
            for (int q = 0; q < 4; ++q) {
                float w = sW[(kc * 4 + q) * GH3 + j];
                #pragma unroll
                for (int g = 0; g < G; ++g) {
                    float xk = (q == 0) ? xv[g].x : (q == 1) ? xv[g].y : (q == 2) ? xv[g].z : xv[g].w;
                    xp[g] += w * xk;
                }
            }
        }
        #pragma unroll 4
        for (int kc = 0; kc < HH / 4; ++kc) {
            float4 hv[G];
            #pragma unroll
            for (int g = 0; g < G; ++g) hv[g] = *(const float4*)&sH[g * HH + kc * 4];
            #pragma unroll
            for (int q = 0; q < 4; ++q) {
                float u = sU[(kc * 4 + q) * GH3 + j];
                #pragma unroll
                for (int g = 0; g < G; ++g) {
                    float hk = (q == 0) ? hv[g].x : (q == 1) ? hv[g].y : (q == 2) ? hv[g].z : hv[g].w;
                    hp[g] += u * hk;
                }
            }
        }
        #pragma unroll
        for (int g = 0; g < G; ++g) { sXP[g * GH3 + j] = xp[g]; sHP[g * GH3 + j] = hp[g]; }
        __syncthreads();

        for (int idx = tid; idx < G * HH; idx += 192) {
            int g  = idx >> 6;
            int jj = idx & 63;
            const float* XP = &sXP[g * GH3];
            const float* HP = &sHP[g * GH3];
            float z = fsigmoid(XP[jj] + HP[jj]);
            float r = fsigmoid(XP[HH + jj] + HP[HH + jj]);
            float n = ftanh(XP[2 * HH + jj] + r * HP[2 * HH + jj]);
            float hold = sH[g * HH + jj];
            float hn = z * hold + (1.0f - z) * n;
            sH[g * HH + jj] = hn;
            g_hid[(b0 + g) * TT * HH + t * HH + jj] = hn;
        }
        __syncthreads();
    }
}

// =================================================================
// logits = hidden @ out_W + out_b   (rows = B*T, cols = 256)
// =================================================================
__global__ __launch_bounds__(256)
void out_kernel(const float* __restrict__ outW, const float* __restrict__ outb,
                float* __restrict__ out)
{
    constexpr int R = 32;
    extern __shared__ float sm[];
    float* sOW = sm;              // 64*256
    float* sOB = sOW + HH * VOC;  // 256
    float* sR  = sOB + VOC;       // 32*64

    const int tid = threadIdx.x;
    for (int i = tid; i < HH * VOC; i += 256) sOW[i] = outW[i];
    sOB[tid] = outb[tid];
    const int rbase = blockIdx.x * R;
    for (int i = tid; i < R * HH; i += 256) sR[i] = g_hid[rbase * HH + i];
    __syncthreads();

    const int v = tid;
    float acc[R];
    #pragma unroll
    for (int r = 0; r < R; ++r) acc[r] = sOB[v];
    for (int k = 0; k < HH; ++k) {
        float w = sOW[k * VOC + v];
        #pragma unroll
        for (int r = 0; r < R; ++r) acc[r] += w * sR[r * HH + k];
    }
    #pragma unroll
    for (int r = 0; r < R; ++r) out[(rbase + r) * VOC + v] = acc[r];
}

// =================================================================
// launch
// =================================================================
extern "C" void kernel_launch(void* const* d_in, const int* in_sizes, int n_in,
                              void* d_out, int out_size)
{
    const int* src_ids = (const int*)d_in[0];   // int32 (JAX x64 disabled)
    const int* tgt_ids = (const int*)d_in[1];   // int32
    const float* src_emb = (const float*)d_in[2];
    const float* enc_Wf  = (const float*)d_in[3];
    const float* enc_Uf  = (const float*)d_in[4];
    const float* enc_bf  = (const float*)d_in[5];
    const float* enc_Wb  = (const float*)d_in[6];
    const float* enc_Ub  = (const float*)d_in[7];
    const float* enc_bb  = (const float*)d_in[8];
    const float* attn_We = (const float*)d_in[9];
    const float* attn_be = (const float*)d_in[10];
    const float* attn_Wd = (const float*)d_in[11];
    const float* attn_bd = (const float*)d_in[12];
    const float* attn_v  = (const float*)d_in[13];
    const float* attn_bv = (const float*)d_in[14];
    const float* dec_W   = (const float*)d_in[15];
    const float* dec_U   = (const float*)d_in[16];
    const float* dec_b   = (const float*)d_in[17];
    const float* out_W   = (const float*)d_in[18];
    const float* out_b   = (const float*)d_in[19];
    float* out = (float*)d_out;

    const int ENC_SMEM  = (24576 + 12288 + 384 + 1024 + 1536 + 1536 + 512) * 4;          // 167424
    const int PROJ_SMEM = (4096 + 64 + 4096) * 4;                                          // 33024
    const int DEC_SMEM  = (24576 + 12288 + 384 + 4096 + 64 + 64 + 4 * 32 * 65 + 512
                           + 768 + 768 + 256 + 256 + 128 + 4) * 4;                         // 209936
    const int OUT_SMEM  = (16384 + 256 + 2048) * 4;                                        // 74752

    cudaFuncSetAttribute(enc_kernel, cudaFuncAttributeMaxDynamicSharedMemorySize, ENC_SMEM);
    cudaFuncSetAttribute(dec_kernel, cudaFuncAttributeMaxDynamicSharedMemorySize, DEC_SMEM);
    cudaFuncSetAttribute(out_kernel, cudaFuncAttributeMaxDynamicSharedMemorySize, OUT_SMEM);

    dim3 enc_grid(BB / 8, 2);
    enc_kernel<<<enc_grid, 192, ENC_SMEM>>>(src_ids, src_emb,
                                            enc_Wf, enc_Uf, enc_bf,
                                            enc_Wb, enc_Ub, enc_bb);
    proj_kernel<<<(BB * SS) / 64, 256, PROJ_SMEM>>>(attn_We, attn_be);
    dec_kernel<<<BB / 4, 192, DEC_SMEM>>>(tgt_ids, dec_W, dec_U, dec_b,
                                          attn_Wd, attn_bd, attn_v, attn_bv, out_W);
    out_kernel<<<(BB * TT) / 32, 256, OUT_SMEM>>>(out_W, out_b, out);
}

// round 9
// speedup vs baseline: 1.0541x; 1.0541x over previous
#include <cuda_runtime.h>

#define BB 4096
#define SS 32
#define TT 32
#define VOC 256
#define EE 128
#define HH 64
#define AA 64
#define GH3 192   /* 3*H */

// ---------------- scratch (device globals; no allocation allowed) ----------------
__device__ float g_fwd[BB * SS * HH];      // forward encoder states
__device__ float g_bwd[BB * SS * HH];      // backward encoder states
__device__ float g_enc[BB * SS * HH];      // encoded = fwd + bwd
__device__ float g_encproj[BB * SS * AA];  // encoded @ attn_We + be
__device__ float g_hid[BB * TT * HH];      // decoder hidden states

// ---------------- packed f32x2 helpers (sm_100+) ----------------
__device__ __forceinline__ unsigned long long pack2(float x) {
    unsigned long long r;
    asm("mov.b64 %0, {%1, %1};" : "=l"(r) : "f"(x));
    return r;
}
__device__ __forceinline__ void fma2(unsigned long long& acc,
                                     unsigned long long a, unsigned long long b) {
    asm("fma.rn.f32x2 %0, %1, %2, %0;" : "+l"(acc) : "l"(a), "l"(b));
}
__device__ __forceinline__ void unpack2(unsigned long long v, float& lo, float& hi) {
    asm("mov.b64 {%0, %1}, %2;" : "=f"(lo), "=f"(hi) : "l"(v));
}

// ---------------- activations ----------------
__device__ __forceinline__ float fsigmoid(float x) {
    return __fdividef(1.0f, 1.0f + __expf(-x));
}
__device__ __forceinline__ float ftanh(float x) {
    float e = __expf(2.0f * x);
    return 1.0f - __fdividef(2.0f, e + 1.0f);
}
// hardware tanh: attention scores only (error does not recurse through h)
__device__ __forceinline__ float tanha(float x) {
    float r; asm("tanh.approx.f32 %0, %1;" : "=f"(r) : "f"(x)); return r;
}

// =================================================================
// Encoder: both directions in one launch (blockIdx.y = dir).
// G=8 batch/block, 192 threads; thread j owns gate column j.
// Activations stored transposed [k][g] so batch pairs form f32x2 lanes.
// =================================================================
__global__ __launch_bounds__(192)
void enc_kernel(const int* __restrict__ src_ids,
                const float* __restrict__ src_emb,
                const float* __restrict__ Wf, const float* __restrict__ Uf,
                const float* __restrict__ bf,
                const float* __restrict__ Wb, const float* __restrict__ Ub,
                const float* __restrict__ bb)
{
    constexpr int G = 8;
    const bool BWD = (blockIdx.y != 0);
    const float* W    = BWD ? Wb : Wf;
    const float* U    = BWD ? Ub : Uf;
    const float* bias = BWD ? bb : bf;
    float* dst        = BWD ? g_bwd : g_fwd;

    extern __shared__ float sm[];
    float* sW  = sm;                    // 128*192
    float* sU  = sW + EE * GH3;         // 64*192
    float* sB  = sU + HH * GH3;         // 384
    float* sXT = sB + 2 * GH3;          // 2 * 128*8 (double buffer, [k][g])
    float* sHT = sXT + 2 * EE * G;      // 64*8  ([k][g])
    float* sXP = sHT + HH * G;          // 8*192
    float* sHP = sXP + G * GH3;         // 8*192

    const int tid = threadIdx.x;
    for (int i = tid; i < EE * GH3; i += 192) sW[i] = W[i];
    for (int i = tid; i < HH * GH3; i += 192) sU[i] = U[i];
    for (int i = tid; i < 2 * GH3; i += 192) sB[i] = bias[i];
    for (int i = tid; i < G * HH; i += 192) sHT[i] = 0.0f;

    const int b0 = blockIdx.x * G;

    // stage step-0 embeddings (transposed)
    {
        const int s0 = BWD ? SS - 1 : 0;
        for (int i = tid; i < G * EE; i += 192) {
            int g = i >> 7, k = i & 127;
            int id = src_ids[(b0 + g) * SS + s0];
            sXT[k * G + g] = src_emb[id * EE + k];
        }
    }
    __syncthreads();

    int cur = 0;
    for (int step = 0; step < SS; ++step) {
        const int s  = BWD ? (SS - 1 - step) : step;
        const int sn = BWD ? (s - 1) : (s + 1);
        float* Xc = &sXT[cur * (EE * G)];
        float* Xn = &sXT[(cur ^ 1) * (EE * G)];

        // prefetch next-step embeddings into registers (hidden under GEMV)
        float pf[6];
        if (step + 1 < SS) {
            int n = 0;
            for (int i = tid; i < G * EE; i += 192) {
                int g = i >> 7, k = i & 127;
                int id = __ldg(&src_ids[(b0 + g) * SS + sn]);
                pf[n++] = __ldg(&src_emb[id * EE + k]);
            }
        }

        const int j = tid;  // gate column 0..191
        unsigned long long xp2[4], hp2[4];
        {
            unsigned long long bx = pack2(sB[j]);
            unsigned long long bh = pack2(sB[GH3 + j]);
            #pragma unroll
            for (int p = 0; p < 4; ++p) { xp2[p] = bx; hp2[p] = bh; }
        }

        #pragma unroll 4
        for (int k = 0; k < EE; ++k) {
            unsigned long long w2 = pack2(sW[k * GH3 + j]);
            ulonglong2 xa = *(const ulonglong2*)&Xc[k * G];
            ulonglong2 xb = *(const ulonglong2*)&Xc[k * G + 4];
            fma2(xp2[0], w2, xa.x); fma2(xp2[1], w2, xa.y);
            fma2(xp2[2], w2, xb.x); fma2(xp2[3], w2, xb.y);
        }
        #pragma unroll 4
        for (int k = 0; k < HH; ++k) {
            unsigned long long u2 = pack2(sU[k * GH3 + j]);
            ulonglong2 ha = *(const ulonglong2*)&sHT[k * G];
            ulonglong2 hb = *(const ulonglong2*)&sHT[k * G + 4];
            fma2(hp2[0], u2, ha.x); fma2(hp2[1], u2, ha.y);
            fma2(hp2[2], u2, hb.x); fma2(hp2[3], u2, hb.y);
        }
        #pragma unroll
        for (int p = 0; p < 4; ++p) {
            float lo, hi;
            unpack2(xp2[p], lo, hi);
            sXP[(2 * p) * GH3 + j] = lo; sXP[(2 * p + 1) * GH3 + j] = hi;
            unpack2(hp2[p], lo, hi);
            sHP[(2 * p) * GH3 + j] = lo; sHP[(2 * p + 1) * GH3 + j] = hi;
        }
        // commit prefetched embeddings to the other buffer
        if (step + 1 < SS) {
            int n = 0;
            for (int i = tid; i < G * EE; i += 192) {
                int g = i >> 7, k = i & 127;
                Xn[k * G + g] = pf[n++];
            }
        }
        __syncthreads();

        // gates (512 tasks over 192 threads)
        for (int idx = tid; idx < G * HH; idx += 192) {
            int g  = idx >> 6;
            int jj = idx & 63;
            const float* XP = &sXP[g * GH3];
            const float* HP = &sHP[g * GH3];
            float z = fsigmoid(XP[jj] + HP[jj]);
            float r = fsigmoid(XP[HH + jj] + HP[HH + jj]);
            float n = ftanh(XP[2 * HH + jj] + r * HP[2 * HH + jj]);
            float hold = sHT[jj * G + g];
            float hn = z * hold + (1.0f - z) * n;
            sHT[jj * G + g] = hn;
            dst[(b0 + g) * SS * HH + s * HH + jj] = hn;
        }
        __syncthreads();
        cur ^= 1;
    }
}

// =================================================================
// encoded = fwd + bwd (fused); enc_proj = encoded @ attn_We + be
// =================================================================
__global__ __launch_bounds__(256)
void proj_kernel(const float* __restrict__ We, const float* __restrict__ be)
{
    extern __shared__ float sm[];
    float* sWe = sm;              // 64*64
    float* sbe = sWe + HH * AA;   // 64
    float* sR  = sbe + 64;        // 64 rows * 64

    const int tid = threadIdx.x;
    for (int i = tid; i < HH * AA; i += 256) sWe[i] = We[i];
    if (tid < 64) sbe[tid] = be[tid];
    const int rbase = blockIdx.x * 64;
    for (int i = tid; i < 64 * HH; i += 256) {
        float e = g_fwd[rbase * HH + i] + g_bwd[rbase * HH + i];
        sR[i] = e;
        g_enc[rbase * HH + i] = e;
    }
    __syncthreads();

    const int a  = tid & 63;
    const int rq = tid >> 6;
    float acc[16];
    #pragma unroll
    for (int r = 0; r < 16; ++r) acc[r] = sbe[a];
    for (int k = 0; k < HH; ++k) {
        float w = sWe[k * AA + a];
        #pragma unroll
        for (int r = 0; r < 16; ++r) acc[r] += w * sR[(rq * 16 + r) * HH + k];
    }
    #pragma unroll
    for (int r = 0; r < 16; ++r)
        g_encproj[(rbase + rq * 16 + r) * AA + a] = acc[r];
}

// =================================================================
// Decoder: Bahdanau attention + GRU. G=4 batch/block, 192 threads.
// Activations transposed [k][g] for f32x2; enc_proj smem pitch 65.
// =================================================================
__global__ __launch_bounds__(192)
void dec_kernel(const int* __restrict__ tgt_ids,
                const float* __restrict__ dW, const float* __restrict__ dU,
                const float* __restrict__ db,
                const float* __restrict__ Wd, const float* __restrict__ bd,
                const float* __restrict__ av, const float* __restrict__ bv,
                const float* __restrict__ outW)
{
    constexpr int G = 4;
    constexpr int EPL = AA + 1;  // 65
    extern __shared__ float sm[];
    float* sW   = sm;                  // 128*192
    float* sU   = sW + 128 * GH3;      // 64*192
    float* sB   = sU + HH * GH3;       // 384
    float* sWd  = sB + 2 * GH3;        // 64*64
    float* sbd  = sWd + HH * AA;       // 64
    float* sv   = sbd + AA;            // 64
    float* sEP  = sv + AA;             // 4*32*65
    float* sInT = sEP + G * SS * EPL;  // 128*4  ([k][g])
    float* sXP  = sInT + 128 * G;      // 4*192
    float* sHP  = sXP + G * GH3;       // 4*192
    float* sHT  = sHP + G * GH3;       // 64*4   ([k][g])
    float* sDP  = sHT + HH * G;        // 4*64
    float* sLg  = sDP + G * AA;        // 4*32
    float* sInv = sLg + G * SS;        // 4

    const int tid = threadIdx.x;
    const int b0 = blockIdx.x * G;

    for (int i = tid; i < 128 * GH3; i += 192) sW[i] = dW[i];
    for (int i = tid; i < HH * GH3; i += 192) sU[i] = dU[i];
    for (int i = tid; i < 2 * GH3; i += 192) sB[i] = db[i];
    for (int i = tid; i < HH * AA; i += 192) sWd[i] = Wd[i];
    if (tid < AA) { sbd[tid] = bd[tid]; sv[tid] = av[tid]; }
    const float bvv = bv[0];

    for (int i = tid; i < G * SS * AA; i += 192) {
        int g = i / (SS * AA);
        int rem = i - g * SS * AA;
        int s = rem >> 6;
        int a = rem & 63;
        sEP[g * SS * EPL + s * EPL + a] = g_encproj[(b0 + g) * SS * AA + rem];
    }
    // h0 = encoded[:, 0] (transposed)
    for (int i = tid; i < G * HH; i += 192) {
        int g = i >> 6; int jj = i & 63;
        sHT[jj * G + g] = g_enc[(b0 + g) * SS * HH + jj];
    }
    __syncthreads();

    for (int t = 0; t < TT; ++t) {
        // dproj = h @ Wd + bd; stage tied-embedding x into sInT rows 0..63
        for (int idx = tid; idx < G * AA; idx += 192) {
            int g = idx >> 6; int a = idx & 63;
            float acc = sbd[a];
            #pragma unroll 8
            for (int h = 0; h < HH; ++h) acc += sHT[h * G + g] * sWd[h * AA + a];
            sDP[g * AA + a] = acc;
            int id = (t == 0) ? 1 : tgt_ids[(b0 + g) * TT + (t - 1)];
            sInT[a * G + g] = __ldg(&outW[a * VOC + id]) * 8.0f;  // tied * sqrt(H)
        }
        __syncthreads();

        // attention scores (hardware tanh)
        for (int idx = tid; idx < G * SS; idx += 192) {
            int g = idx >> 5; int s = idx & 31;
            const float* ep = &sEP[g * SS * EPL + s * EPL];
            const float* dp = &sDP[g * AA];
            float acc = bvv;
            #pragma unroll 8
            for (int a = 0; a < AA; ++a) acc += sv[a] * tanha(dp[a] + ep[a]);
            sLg[g * SS + s] = acc;
        }
        __syncthreads();

        // softmax over S
        if (tid < G) {
            int g = tid;
            float m = -1e30f;
            for (int s = 0; s < SS; ++s) m = fmaxf(m, sLg[g * SS + s]);
            float sum = 0.0f;
            for (int s = 0; s < SS; ++s) {
                float e = __expf(sLg[g * SS + s] - m);
                sLg[g * SS + s] = e;
                sum += e;
            }
            sInv[g] = __fdividef(1.0f, sum);
        }
        __syncthreads();

        // context -> sInT rows 64..127
        for (int idx = tid; idx < G * HH; idx += 192) {
            int g = idx >> 6; int h = idx & 63;
            const float* encb = &g_enc[(b0 + g) * SS * HH];
            float acc = 0.0f;
            #pragma unroll
            for (int s = 0; s < SS; ++s) acc += sLg[g * SS + s] * __ldg(&encb[s * HH + h]);
            sInT[(HH + h) * G + g] = acc * sInv[g];
        }
        __syncthreads();

        // GRU GEMV, f32x2
        const int j = tid;
        unsigned long long xp2[2], hp2[2];
        {
            unsigned long long bx = pack2(sB[j]);
            unsigned long long bh = pack2(sB[GH3 + j]);
            xp2[0] = bx; xp2[1] = bx; hp2[0] = bh; hp2[1] = bh;
        }
        #pragma unroll 4
        for (int k = 0; k < 128; ++k) {
            unsigned long long w2 = pack2(sW[k * GH3 + j]);
            ulonglong2 xv = *(const ulonglong2*)&sInT[k * G];
            fma2(xp2[0], w2, xv.x); fma2(xp2[1], w2, xv.y);
        }
        #pragma unroll 4
        for (int k = 0; k < HH; ++k) {
            unsigned long long u2 = pack2(sU[k * GH3 + j]);
            ulonglong2 hv = *(const ulonglong2*)&sHT[k * G];
            fma2(hp2[0], u2, hv.x); fma2(hp2[1], u2, hv.y);
        }
        #pragma unroll
        for (int p = 0; p < 2; ++p) {
            float lo, hi;
            unpack2(xp2[p], lo, hi);
            sXP[(2 * p) * GH3 + j] = lo; sXP[(2 * p + 1) * GH3 + j] = hi;
            unpack2(hp2[p], lo, hi);
            sHP[(2 * p) * GH3 + j] = lo; sHP[(2 * p + 1) * GH3 + j] = hi;
        }
        __syncthreads();

        for (int idx = tid; idx < G * HH; idx += 192) {
            int g  = idx >> 6;
            int jj = idx & 63;
            const float* XP = &sXP[g * GH3];
            const float* HP = &sHP[g * GH3];
            float z = fsigmoid(XP[jj] + HP[jj]);
            float r = fsigmoid(XP[HH + jj] + HP[HH + jj]);
            float n = ftanh(XP[2 * HH + jj] + r * HP[2 * HH + jj]);
            float hold = sHT[jj * G + g];
            float hn = z * hold + (1.0f - z) * n;
            sHT[jj * G + g] = hn;
            g_hid[(b0 + g) * TT * HH + t * HH + jj] = hn;
        }
        __syncthreads();
    }
}

// =================================================================
// logits = hidden @ out_W + out_b; 8 row-tiles per block to amortize
// the 66KB weight prologue (grid 4096 -> 512).
// =================================================================
__global__ __launch_bounds__(256)
void out_kernel(const float* __restrict__ outW, const float* __restrict__ outb,
                float* __restrict__ out)
{
    constexpr int R = 32;
    extern __shared__ float sm[];
    float* sOW = sm;              // 64*256
    float* sOB = sOW + HH * VOC;  // 256
    float* sR  = sOB + VOC;       // 32*64

    const int tid = threadIdx.x;
    for (int i = tid; i < HH * VOC; i += 256) sOW[i] = outW[i];
    sOB[tid] = outb[tid];

    for (int tile = 0; tile < 8; ++tile) {
        const int rbase = (blockIdx.x * 8 + tile) * R;
        __syncthreads();  // sR reuse barrier (also covers sOW staging at tile 0)
        for (int i = tid; i < R * HH; i += 256) sR[i] = g_hid[rbase * HH + i];
        __syncthreads();

        const int v = tid;
        float acc[R];
        #pragma unroll
        for (int r = 0; r < R; ++r) acc[r] = sOB[v];
        for (int k = 0; k < HH; ++k) {
            float w = sOW[k * VOC + v];
            #pragma unroll
            for (int r = 0; r < R; ++r) acc[r] += w * sR[r * HH + k];
        }
        #pragma unroll
        for (int r = 0; r < R; ++r) out[(rbase + r) * VOC + v] = acc[r];
    }
}

// =================================================================
// launch
// =================================================================
extern "C" void kernel_launch(void* const* d_in, const int* in_sizes, int n_in,
                              void* d_out, int out_size)
{
    const int* src_ids = (const int*)d_in[0];   // int32 (JAX x64 disabled)
    const int* tgt_ids = (const int*)d_in[1];   // int32
    const float* src_emb = (const float*)d_in[2];
    const float* enc_Wf  = (const float*)d_in[3];
    const float* enc_Uf  = (const float*)d_in[4];
    const float* enc_bf  = (const float*)d_in[5];
    const float* enc_Wb  = (const float*)d_in[6];
    const float* enc_Ub  = (const float*)d_in[7];
    const float* enc_bb  = (const float*)d_in[8];
    const float* attn_We = (const float*)d_in[9];
    const float* attn_be = (const float*)d_in[10];
    const float* attn_Wd = (const float*)d_in[11];
    const float* attn_bd = (const float*)d_in[12];
    const float* attn_v  = (const float*)d_in[13];
    const float* attn_bv = (const float*)d_in[14];
    const float* dec_W   = (const float*)d_in[15];
    const float* dec_U   = (const float*)d_in[16];
    const float* dec_b   = (const float*)d_in[17];
    const float* out_W   = (const float*)d_in[18];
    const float* out_b   = (const float*)d_in[19];
    float* out = (float*)d_out;

    const int ENC_SMEM  = (24576 + 12288 + 384 + 2048 + 512 + 1536 + 1536) * 4;  // 171520
    const int PROJ_SMEM = (4096 + 64 + 4096) * 4;                                  // 33024
    const int DEC_SMEM  = (24576 + 12288 + 384 + 4096 + 64 + 64 + 4 * 32 * 65
                           + 512 + 768 + 768 + 256 + 256 + 128 + 4) * 4;           // 209936
    const int OUT_SMEM  = (16384 + 256 + 2048) * 4;                                // 74752

    cudaFuncSetAttribute(enc_kernel, cudaFuncAttributeMaxDynamicSharedMemorySize, ENC_SMEM);
    cudaFuncSetAttribute(dec_kernel, cudaFuncAttributeMaxDynamicSharedMemorySize, DEC_SMEM);
    cudaFuncSetAttribute(out_kernel, cudaFuncAttributeMaxDynamicSharedMemorySize, OUT_SMEM);

    dim3 enc_grid(BB / 8, 2);
    enc_kernel<<<enc_grid, 192, ENC_SMEM>>>(src_ids, src_emb,
                                            enc_Wf, enc_Uf, enc_bf,
                                            enc_Wb, enc_Ub, enc_bb);
    proj_kernel<<<(BB * SS) / 64, 256, PROJ_SMEM>>>(attn_We, attn_be);
    dec_kernel<<<BB / 4, 192, DEC_SMEM>>>(tgt_ids, dec_W, dec_U, dec_b,
                                          attn_Wd, attn_bd, attn_v, attn_bv, out_W);
    out_kernel<<<(BB * TT) / (32 * 8), 256, OUT_SMEM>>>(out_W, out_b, out);
}

// round 10
// speedup vs baseline: 1.3364x; 1.2678x over previous
#include <cuda_runtime.h>

#define BB 4096
#define SS 32
#define TT 32
#define VOC 256
#define EE 128
#define HH 64
#define AA 64
#define GH3 192   /* 3*H */

// ---------------- scratch (device globals; no allocation allowed) ----------------
__device__ float g_fwd[BB * SS * HH];      // forward encoder states
__device__ float g_bwd[BB * SS * HH];      // backward encoder states
__device__ float g_enc[BB * SS * HH];      // encoded = fwd + bwd
__device__ float g_encproj[BB * SS * AA];  // encoded @ attn_We + be
__device__ float g_hid[BB * TT * HH];      // decoder hidden states

// ---------------- packed f32x2 helpers (sm_100+) ----------------
__device__ __forceinline__ unsigned long long pack2(float x) {
    unsigned long long r;
    asm("mov.b64 %0, {%1, %1};" : "=l"(r) : "f"(x));
    return r;
}
__device__ __forceinline__ void fma2(unsigned long long& acc,
                                     unsigned long long a, unsigned long long b) {
    asm("fma.rn.f32x2 %0, %1, %2, %0;" : "+l"(acc) : "l"(a), "l"(b));
}
__device__ __forceinline__ void unpack2(unsigned long long v, float& lo, float& hi) {
    asm("mov.b64 {%0, %1}, %2;" : "=f"(lo), "=f"(hi) : "l"(v));
}

// ---------------- activations ----------------
__device__ __forceinline__ float fsigmoid(float x) {
    return __fdividef(1.0f, 1.0f + __expf(-x));
}
__device__ __forceinline__ float ftanh(float x) {
    float e = __expf(2.0f * x);
    return 1.0f - __fdividef(2.0f, e + 1.0f);
}
// hardware tanh: attention scores only (error does not recurse through h)
__device__ __forceinline__ float tanha(float x) {
    float r; asm("tanh.approx.f32 %0, %1;" : "=f"(r) : "f"(x)); return r;
}

// =================================================================
// Encoder: both directions in one launch (blockIdx.y = dir).
// G=8 batch/block, 384 threads: 2 threads per gate column (k-split),
// partial sums combined in the gate phase. Activations transposed
// [k][g] so batch pairs form f32x2 lanes.
// =================================================================
__global__ __launch_bounds__(384)
void enc_kernel(const int* __restrict__ src_ids,
                const float* __restrict__ src_emb,
                const float* __restrict__ Wf, const float* __restrict__ Uf,
                const float* __restrict__ bf,
                const float* __restrict__ Wb, const float* __restrict__ Ub,
                const float* __restrict__ bb)
{
    constexpr int G = 8;
    constexpr int NT = 384;
    const bool BWD = (blockIdx.y != 0);
    const float* W    = BWD ? Wb : Wf;
    const float* U    = BWD ? Ub : Uf;
    const float* bias = BWD ? bb : bf;
    float* dst        = BWD ? g_bwd : g_fwd;

    extern __shared__ float sm[];
    float* sW  = sm;                    // 128*192
    float* sU  = sW + EE * GH3;         // 64*192
    float* sB  = sU + HH * GH3;         // 384
    float* sXT = sB + 2 * GH3;          // 2 * 128*8 (double buffer, [k][g])
    float* sHT = sXT + 2 * EE * G;      // 64*8  ([k][g])
    float* sXP = sHT + HH * G;          // 2 halves * 8 * 192
    float* sHP = sXP + 2 * G * GH3;     // 2 halves * 8 * 192

    const int tid = threadIdx.x;
    for (int i = tid; i < EE * GH3; i += NT) sW[i] = W[i];
    for (int i = tid; i < HH * GH3; i += NT) sU[i] = U[i];
    for (int i = tid; i < 2 * GH3; i += NT) sB[i] = bias[i];
    for (int i = tid; i < G * HH; i += NT) sHT[i] = 0.0f;

    const int b0 = blockIdx.x * G;
    const int half = tid / 192;        // 0 or 1 (warp-uniform: 192 = 6 warps)
    const int j    = tid - half * 192; // gate column 0..191

    // stage step-0 embeddings (transposed)
    {
        const int s0 = BWD ? SS - 1 : 0;
        for (int i = tid; i < G * EE; i += NT) {
            int g = i >> 7, k = i & 127;
            int id = src_ids[(b0 + g) * SS + s0];
            sXT[k * G + g] = src_emb[id * EE + k];
        }
    }
    __syncthreads();

    int cur = 0;
    for (int step = 0; step < SS; ++step) {
        const int s  = BWD ? (SS - 1 - step) : step;
        const int sn = BWD ? (s - 1) : (s + 1);
        float* Xc = &sXT[cur * (EE * G)];
        float* Xn = &sXT[(cur ^ 1) * (EE * G)];

        // prefetch next-step embeddings into registers (hidden under GEMV)
        float pf[3];
        if (step + 1 < SS) {
            int n = 0;
            for (int i = tid; i < G * EE; i += NT) {
                int g = i >> 7, k = i & 127;
                int id = __ldg(&src_ids[(b0 + g) * SS + sn]);
                pf[n++] = __ldg(&src_emb[id * EE + k]);
            }
        }

        // GEMV: this thread covers k in [half*64, half*64+64) of W and
        // [half*32, half*32+32) of U, for column j, all 8 batch elems.
        unsigned long long xp2[4], hp2[4];
        {
            unsigned long long bx = (half == 0) ? pack2(sB[j]) : 0ULL;
            unsigned long long bh = (half == 0) ? pack2(sB[GH3 + j]) : 0ULL;
            #pragma unroll
            for (int p = 0; p < 4; ++p) { xp2[p] = bx; hp2[p] = bh; }
        }

        const int kw0 = half * 64;
        #pragma unroll 4
        for (int kk = 0; kk < 64; ++kk) {
            int k = kw0 + kk;
            unsigned long long w2 = pack2(sW[k * GH3 + j]);
            ulonglong2 xa = *(const ulonglong2*)&Xc[k * G];
            ulonglong2 xb = *(const ulonglong2*)&Xc[k * G + 4];
            fma2(xp2[0], w2, xa.x); fma2(xp2[1], w2, xa.y);
            fma2(xp2[2], w2, xb.x); fma2(xp2[3], w2, xb.y);
        }
        const int ku0 = half * 32;
        #pragma unroll 4
        for (int kk = 0; kk < 32; ++kk) {
            int k = ku0 + kk;
            unsigned long long u2 = pack2(sU[k * GH3 + j]);
            ulonglong2 ha = *(const ulonglong2*)&sHT[k * G];
            ulonglong2 hb = *(const ulonglong2*)&sHT[k * G + 4];
            fma2(hp2[0], u2, ha.x); fma2(hp2[1], u2, ha.y);
            fma2(hp2[2], u2, hb.x); fma2(hp2[3], u2, hb.y);
        }
        #pragma unroll
        for (int p = 0; p < 4; ++p) {
            float lo, hi;
            unpack2(xp2[p], lo, hi);
            sXP[(half * G + 2 * p) * GH3 + j] = lo;
            sXP[(half * G + 2 * p + 1) * GH3 + j] = hi;
            unpack2(hp2[p], lo, hi);
            sHP[(half * G + 2 * p) * GH3 + j] = lo;
            sHP[(half * G + 2 * p + 1) * GH3 + j] = hi;
        }
        // commit prefetched embeddings to the other buffer
        if (step + 1 < SS) {
            int n = 0;
            for (int i = tid; i < G * EE; i += NT) {
                int g = i >> 7, k = i & 127;
                Xn[k * G + g] = pf[n++];
            }
        }
        __syncthreads();

        // gates (512 tasks over 384 threads); sum the two k-halves
        for (int idx = tid; idx < G * HH; idx += NT) {
            int g  = idx >> 6;
            int jj = idx & 63;
            const float* XP0 = &sXP[g * GH3];
            const float* XP1 = &sXP[(G + g) * GH3];
            const float* HP0 = &sHP[g * GH3];
            const float* HP1 = &sHP[(G + g) * GH3];
            float xz = XP0[jj] + XP1[jj],           hz = HP0[jj] + HP1[jj];
            float xr = XP0[HH + jj] + XP1[HH + jj], hr = HP0[HH + jj] + HP1[HH + jj];
            float xh = XP0[2*HH + jj] + XP1[2*HH + jj];
            float hh = HP0[2*HH + jj] + HP1[2*HH + jj];
            float z = fsigmoid(xz + hz);
            float r = fsigmoid(xr + hr);
            float n = ftanh(xh + r * hh);
            float hold = sHT[jj * G + g];
            float hn = z * hold + (1.0f - z) * n;
            sHT[jj * G + g] = hn;
            dst[(b0 + g) * SS * HH + s * HH + jj] = hn;
        }
        __syncthreads();
        cur ^= 1;
    }
}

// =================================================================
// encoded = fwd + bwd (fused); enc_proj = encoded @ attn_We + be
// =================================================================
__global__ __launch_bounds__(256)
void proj_kernel(const float* __restrict__ We, const float* __restrict__ be)
{
    extern __shared__ float sm[];
    float* sWe = sm;              // 64*64
    float* sbe = sWe + HH * AA;   // 64
    float* sR  = sbe + 64;        // 64 rows * 64

    const int tid = threadIdx.x;
    for (int i = tid; i < HH * AA; i += 256) sWe[i] = We[i];
    if (tid < 64) sbe[tid] = be[tid];
    const int rbase = blockIdx.x * 64;
    for (int i = tid; i < 64 * HH; i += 256) {
        float e = g_fwd[rbase * HH + i] + g_bwd[rbase * HH + i];
        sR[i] = e;
        g_enc[rbase * HH + i] = e;
    }
    __syncthreads();

    const int a  = tid & 63;
    const int rq = tid >> 6;
    float acc[16];
    #pragma unroll
    for (int r = 0; r < 16; ++r) acc[r] = sbe[a];
    for (int k = 0; k < HH; ++k) {
        float w = sWe[k * AA + a];
        #pragma unroll
        for (int r = 0; r < 16; ++r) acc[r] += w * sR[(rq * 16 + r) * HH + k];
    }
    #pragma unroll
    for (int r = 0; r < 16; ++r)
        g_encproj[(rbase + rq * 16 + r) * AA + a] = acc[r];
}

// =================================================================
// Decoder: Bahdanau attention + GRU. G=4 batch/block, 384 threads,
// k-split GEMV. enc_proj cached in smem (pitch 65); warp softmax.
// =================================================================
__global__ __launch_bounds__(384)
void dec_kernel(const int* __restrict__ tgt_ids,
                const float* __restrict__ dW, const float* __restrict__ dU,
                const float* __restrict__ db,
                const float* __restrict__ Wd, const float* __restrict__ bd,
                const float* __restrict__ av, const float* __restrict__ bv,
                const float* __restrict__ outW)
{
    constexpr int G = 4;
    constexpr int NT = 384;
    constexpr int EPL = AA + 1;  // 65
    extern __shared__ float sm[];
    float* sW   = sm;                  // 128*192
    float* sU   = sW + 128 * GH3;      // 64*192
    float* sB   = sU + HH * GH3;       // 384
    float* sWd  = sB + 2 * GH3;        // 64*64
    float* sbd  = sWd + HH * AA;       // 64
    float* sv   = sbd + AA;            // 64
    float* sEP  = sv + AA;             // 4*32*65
    float* sInT = sEP + G * SS * EPL;  // 128*4  ([k][g])
    float* sXP  = sInT + 128 * G;      // 2 halves * 4 * 192
    float* sHP  = sXP + 2 * G * GH3;   // 2 halves * 4 * 192
    float* sHT  = sHP + 2 * G * GH3;   // 64*4   ([k][g])
    float* sDP  = sHT + HH * G;        // 4*64
    float* sLg  = sDP + G * AA;        // 4*32
    float* sInv = sLg + G * SS;        // 4

    const int tid = threadIdx.x;
    const int b0 = blockIdx.x * G;
    const int half = tid / 192;
    const int j    = tid - half * 192;

    for (int i = tid; i < 128 * GH3; i += NT) sW[i] = dW[i];
    for (int i = tid; i < HH * GH3; i += NT) sU[i] = dU[i];
    for (int i = tid; i < 2 * GH3; i += NT) sB[i] = db[i];
    for (int i = tid; i < HH * AA; i += NT) sWd[i] = Wd[i];
    if (tid < AA) { sbd[tid] = bd[tid]; sv[tid] = av[tid]; }
    const float bvv = bv[0];

    for (int i = tid; i < G * SS * AA; i += NT) {
        int g = i / (SS * AA);
        int rem = i - g * SS * AA;
        int s = rem >> 6;
        int a = rem & 63;
        sEP[g * SS * EPL + s * EPL + a] = g_encproj[(b0 + g) * SS * AA + rem];
    }
    // h0 = encoded[:, 0] (transposed)
    for (int i = tid; i < G * HH; i += NT) {
        int g = i >> 6; int jj = i & 63;
        sHT[jj * G + g] = g_enc[(b0 + g) * SS * HH + jj];
    }
    __syncthreads();

    for (int t = 0; t < TT; ++t) {
        // dproj = h @ Wd + bd; stage tied-embedding x into sInT rows 0..63
        for (int idx = tid; idx < G * AA; idx += NT) {
            int g = idx >> 6; int a = idx & 63;
            float acc = sbd[a];
            #pragma unroll 8
            for (int h = 0; h < HH; ++h) acc += sHT[h * G + g] * sWd[h * AA + a];
            sDP[g * AA + a] = acc;
            int id = (t == 0) ? 1 : tgt_ids[(b0 + g) * TT + (t - 1)];
            sInT[a * G + g] = __ldg(&outW[a * VOC + id]) * 8.0f;  // tied * sqrt(H)
        }
        __syncthreads();

        // attention scores (hardware tanh); 128 tasks
        if (tid < G * SS) {
            int g = tid >> 5; int s = tid & 31;
            const float* ep = &sEP[g * SS * EPL + s * EPL];
            const float* dp = &sDP[g * AA];
            float acc = bvv;
            #pragma unroll 8
            for (int a = 0; a < AA; ++a) acc += sv[a] * tanha(dp[a] + ep[a]);
            sLg[g * SS + s] = acc;
        }
        __syncthreads();

        // softmax over S: one warp per batch element (4 warps)
        if (tid < G * 32) {
            int g = tid >> 5, lane = tid & 31;
            float x = sLg[g * SS + lane];
            float m = x;
            #pragma unroll
            for (int off = 16; off > 0; off >>= 1)
                m = fmaxf(m, __shfl_xor_sync(0xffffffffu, m, off));
            float e = __expf(x - m);
            float sum = e;
            #pragma unroll
            for (int off = 16; off > 0; off >>= 1)
                sum += __shfl_xor_sync(0xffffffffu, sum, off);
            sLg[g * SS + lane] = e;
            if (lane == 0) sInv[g] = __fdividef(1.0f, sum);
        }
        __syncthreads();

        // context -> sInT rows 64..127 (256 tasks)
        if (tid < G * HH) {
            int g = tid >> 6; int h = tid & 63;
            const float* encb = &g_enc[(b0 + g) * SS * HH];
            float acc = 0.0f;
            #pragma unroll
            for (int s = 0; s < SS; ++s) acc += sLg[g * SS + s] * __ldg(&encb[s * HH + h]);
            sInT[(HH + h) * G + g] = acc * sInv[g];
        }
        __syncthreads();

        // GRU GEMV, f32x2, k-split across halves
        unsigned long long xp2[2], hp2[2];
        {
            unsigned long long bx = (half == 0) ? pack2(sB[j]) : 0ULL;
            unsigned long long bh = (half == 0) ? pack2(sB[GH3 + j]) : 0ULL;
            xp2[0] = bx; xp2[1] = bx; hp2[0] = bh; hp2[1] = bh;
        }
        const int kw0 = half * 64;
        #pragma unroll 4
        for (int kk = 0; kk < 64; ++kk) {
            int k = kw0 + kk;
            unsigned long long w2 = pack2(sW[k * GH3 + j]);
            ulonglong2 xv = *(const ulonglong2*)&sInT[k * G];
            fma2(xp2[0], w2, xv.x); fma2(xp2[1], w2, xv.y);
        }
        const int ku0 = half * 32;
        #pragma unroll 4
        for (int kk = 0; kk < 32; ++kk) {
            int k = ku0 + kk;
            unsigned long long u2 = pack2(sU[k * GH3 + j]);
            ulonglong2 hv = *(const ulonglong2*)&sHT[k * G];
            fma2(hp2[0], u2, hv.x); fma2(hp2[1], u2, hv.y);
        }
        #pragma unroll
        for (int p = 0; p < 2; ++p) {
            float lo, hi;
            unpack2(xp2[p], lo, hi);
            sXP[(half * G + 2 * p) * GH3 + j] = lo;
            sXP[(half * G + 2 * p + 1) * GH3 + j] = hi;
            unpack2(hp2[p], lo, hi);
            sHP[(half * G + 2 * p) * GH3 + j] = lo;
            sHP[(half * G + 2 * p + 1) * GH3 + j] = hi;
        }
        __syncthreads();

        // gates (256 tasks); sum the two k-halves
        if (tid < G * HH) {
            int g  = tid >> 6;
            int jj = tid & 63;
            const float* XP0 = &sXP[g * GH3];
            const float* XP1 = &sXP[(G + g) * GH3];
            const float* HP0 = &sHP[g * GH3];
            const float* HP1 = &sHP[(G + g) * GH3];
            float xz = XP0[jj] + XP1[jj],           hz = HP0[jj] + HP1[jj];
            float xr = XP0[HH + jj] + XP1[HH + jj], hr = HP0[HH + jj] + HP1[HH + jj];
            float xh = XP0[2*HH + jj] + XP1[2*HH + jj];
            float hh = HP0[2*HH + jj] + HP1[2*HH + jj];
            float z = fsigmoid(xz + hz);
            float r = fsigmoid(xr + hr);
            float n = ftanh(xh + r * hh);
            float hold = sHT[jj * G + g];
            float hn = z * hold + (1.0f - z) * n;
            sHT[jj * G + g] = hn;
            g_hid[(b0 + g) * TT * HH + t * HH + jj] = hn;
        }
        __syncthreads();
    }
}

// =================================================================
// logits = hidden @ out_W + out_b. Transposed row tile (pitch 36,
// 16B-aligned rows) + f32x2 over row pairs: per k = 1 LDS + 1 pack +
// 8 LDS.128 (broadcast) + 16 fma2. 4 tiles/block, grid 1024.
// =================================================================
__global__ __launch_bounds__(256)
void out_kernel(const float* __restrict__ outW, const float* __restrict__ outb,
                float* __restrict__ out)
{
    constexpr int R = 32;
    constexpr int TIL = 4;
    constexpr int PIT = 36;  // floats; 144B rows keep 16B alignment
    extern __shared__ float sm[];
    float* sOW = sm;              // 64*256
    float* sOB = sOW + HH * VOC;  // 256
    float* sRT = sOB + VOC;       // 64 * 36 (transposed tile [k][r])

    const int tid = threadIdx.x;
    for (int i = tid; i < HH * VOC; i += 256) sOW[i] = outW[i];
    sOB[tid] = outb[tid];

    for (int tile = 0; tile < TIL; ++tile) {
        const int rbase = (blockIdx.x * TIL + tile) * R;
        __syncthreads();  // sRT reuse barrier (covers sOW staging at tile 0)
        for (int i = tid; i < R * HH; i += 256) {
            int r = i >> 6, k = i & 63;               // coalesced gmem read
            sRT[k * PIT + r] = g_hid[(rbase + r) * HH + k];
        }
        __syncthreads();

        const int v = tid;
        const unsigned long long b2 = pack2(sOB[v]);
        unsigned long long acc2[16];
        #pragma unroll
        for (int p = 0; p < 16; ++p) acc2[p] = b2;

        #pragma unroll 4
        for (int k = 0; k < HH; ++k) {
            unsigned long long w2 = pack2(sOW[k * VOC + v]);
            const ulonglong2* row = (const ulonglong2*)&sRT[k * PIT];
            #pragma unroll
            for (int q = 0; q < 8; ++q) {
                ulonglong2 rp = row[q];
                fma2(acc2[2 * q], w2, rp.x);
                fma2(acc2[2 * q + 1], w2, rp.y);
            }
        }
        #pragma unroll
        for (int p = 0; p < 16; ++p) {
            float lo, hi;
            unpack2(acc2[p], lo, hi);
            out[(rbase + 2 * p) * VOC + v] = lo;
            out[(rbase + 2 * p + 1) * VOC + v] = hi;
        }
    }
}

// =================================================================
// launch
// =================================================================
extern "C" void kernel_launch(void* const* d_in, const int* in_sizes, int n_in,
                              void* d_out, int out_size)
{
    const int* src_ids = (const int*)d_in[0];   // int32 (JAX x64 disabled)
    const int* tgt_ids = (const int*)d_in[1];   // int32
    const float* src_emb = (const float*)d_in[2];
    const float* enc_Wf  = (const float*)d_in[3];
    const float* enc_Uf  = (const float*)d_in[4];
    const float* enc_bf  = (const float*)d_in[5];
    const float* enc_Wb  = (const float*)d_in[6];
    const float* enc_Ub  = (const float*)d_in[7];
    const float* enc_bb  = (const float*)d_in[8];
    const float* attn_We = (const float*)d_in[9];
    const float* attn_be = (const float*)d_in[10];
    const float* attn_Wd = (const float*)d_in[11];
    const float* attn_bd = (const float*)d_in[12];
    const float* attn_v  = (const float*)d_in[13];
    const float* attn_bv = (const float*)d_in[14];
    const float* dec_W   = (const float*)d_in[15];
    const float* dec_U   = (const float*)d_in[16];
    const float* dec_b   = (const float*)d_in[17];
    const float* out_W   = (const float*)d_in[18];
    const float* out_b   = (const float*)d_in[19];
    float* out = (float*)d_out;

    const int ENC_SMEM  = (24576 + 12288 + 384 + 2048 + 512 + 3072 + 3072) * 4;  // 183808
    const int PROJ_SMEM = (4096 + 64 + 4096) * 4;                                  // 33024
    const int DEC_SMEM  = (24576 + 12288 + 384 + 4096 + 64 + 64 + 4 * 32 * 65
                           + 512 + 1536 + 1536 + 256 + 256 + 128 + 4) * 4;         // 216080
    const int OUT_SMEM  = (16384 + 256 + 64 * 36) * 4;                             // 75776

    cudaFuncSetAttribute(enc_kernel, cudaFuncAttributeMaxDynamicSharedMemorySize, ENC_SMEM);
    cudaFuncSetAttribute(dec_kernel, cudaFuncAttributeMaxDynamicSharedMemorySize, DEC_SMEM);
    cudaFuncSetAttribute(out_kernel, cudaFuncAttributeMaxDynamicSharedMemorySize, OUT_SMEM);

    dim3 enc_grid(BB / 8, 2);
    enc_kernel<<<enc_grid, 384, ENC_SMEM>>>(src_ids, src_emb,
                                            enc_Wf, enc_Uf, enc_bf,
                                            enc_Wb, enc_Ub, enc_bb);
    proj_kernel<<<(BB * SS) / 64, 256, PROJ_SMEM>>>(attn_We, attn_be);
    dec_kernel<<<BB / 4, 384, DEC_SMEM>>>(tgt_ids, dec_W, dec_U, dec_b,
                                          attn_Wd, attn_bd, attn_v, attn_bv, out_W);
    out_kernel<<<(BB * TT) / (32 * 4), 256, OUT_SMEM>>>(out_W, out_b, out);
}

// round 11
// speedup vs baseline: 2.1188x; 1.5855x over previous
#include <cuda_runtime.h>

#define BB 4096
#define SS 32
#define TT 32
#define VOC 256
#define EE 128
#define HH 64
#define AA 64
#define GH3 192   /* 3*H */

// ---------------- scratch (device globals; no allocation allowed) ----------------
__device__ float g_fwd[BB * SS * HH];      // forward encoder states
__device__ float g_bwd[BB * SS * HH];      // backward encoder states
__device__ float g_enc[BB * SS * HH];      // encoded = fwd + bwd
__device__ float g_encproj[BB * SS * AA];  // encoded @ attn_We + be
__device__ float g_hid[BB * TT * HH];      // decoder hidden states
__device__ float g_TWf[VOC * GH3];         // table: emb[id] @ enc_Wf + bf[0]
__device__ float g_TWb[VOC * GH3];         // table: emb[id] @ enc_Wb + bb[0]
__device__ float g_TD[VOC * GH3];          // table: tied_emb[id] @ dec_W[0:64] + db[0]

// ---------------- packed f32x2 helpers (sm_100+) ----------------
__device__ __forceinline__ unsigned long long pack2(float x) {
    unsigned long long r;
    asm("mov.b64 %0, {%1, %1};" : "=l"(r) : "f"(x));
    return r;
}
__device__ __forceinline__ void fma2(unsigned long long& acc,
                                     unsigned long long a, unsigned long long b) {
    asm("fma.rn.f32x2 %0, %1, %2, %0;" : "+l"(acc) : "l"(a), "l"(b));
}
__device__ __forceinline__ void unpack2(unsigned long long v, float& lo, float& hi) {
    asm("mov.b64 {%0, %1}, %2;" : "=f"(lo), "=f"(hi) : "l"(v));
}

// ---------------- activations ----------------
__device__ __forceinline__ float fsigmoid(float x) {
    return __fdividef(1.0f, 1.0f + __expf(-x));
}
__device__ __forceinline__ float ftanh(float x) {
    float e = __expf(2.0f * x);
    return 1.0f - __fdividef(2.0f, e + 1.0f);
}
__device__ __forceinline__ float tanha(float x) {
    float r; asm("tanh.approx.f32 %0, %1;" : "=f"(r) : "f"(x)); return r;
}

// =================================================================
// Precompute per-vocab-id input-projection tables (V=256 rows).
//   g_TWf[id] = emb[id] @ Wf + bf[0]
//   g_TWb[id] = emb[id] @ Wb + bb[0]
//   g_TD[id]  = (outW.T[id]*sqrt(H)) @ dec_W[0:64] + db[0]
// =================================================================
__global__ __launch_bounds__(192)
void table_kernel(const float* __restrict__ src_emb,
                  const float* __restrict__ Wf, const float* __restrict__ bf,
                  const float* __restrict__ Wb, const float* __restrict__ bb,
                  const float* __restrict__ dW, const float* __restrict__ db,
                  const float* __restrict__ outW)
{
    __shared__ float se[EE];
    __shared__ float sx[HH];
    const int id = blockIdx.x;
    const int j = threadIdx.x;
    for (int i = j; i < EE; i += 192) se[i] = src_emb[id * EE + i];
    for (int i = j; i < HH; i += 192) sx[i] = outW[i * VOC + id] * 8.0f;
    __syncthreads();

    float af = bf[j], ab = bb[j];
    #pragma unroll 4
    for (int k = 0; k < EE; ++k) {
        af += se[k] * Wf[k * GH3 + j];
        ab += se[k] * Wb[k * GH3 + j];
    }
    float ad = db[j];
    #pragma unroll 4
    for (int h = 0; h < HH; ++h) ad += sx[h] * dW[h * GH3 + j];
    g_TWf[id * GH3 + j] = af;
    g_TWb[id * GH3 + j] = ab;
    g_TD[id * GH3 + j]  = ad;
}

// =================================================================
// Encoder: both directions in one launch (blockIdx.y = dir).
// x-projection comes from the table (gather, double-buffered).
// Loop does ONLY h @ U. G=16 batch/block, 384 threads (2-way k-split),
// 104 KB smem -> 2 CTAs/SM.
// =================================================================
__global__ __launch_bounds__(384)
void enc_kernel(const int* __restrict__ src_ids,
                const float* __restrict__ Uf, const float* __restrict__ bf,
                const float* __restrict__ Ub, const float* __restrict__ bb)
{
    constexpr int G = 16;
    constexpr int NT = 384;
    const bool BWD = (blockIdx.y != 0);
    const float* U    = BWD ? Ub : Uf;
    const float* bias = BWD ? bb : bf;
    const float* TW   = BWD ? g_TWb : g_TWf;
    float* dst        = BWD ? g_bwd : g_fwd;

    extern __shared__ float sm[];
    float* sU  = sm;                 // 64*192 = 12288
    float* sB  = sU + HH * GH3;      // 384
    float* sXT = sB + 2 * GH3;       // 2 * 16*192 = 6144 (double buffer, [g][192])
    float* sHT = sXT + 2 * G * GH3;  // 64*16 = 1024 ([k][g])
    float* sHP = sHT + HH * G;       // 2 halves * 16*192 = 6144

    const int tid = threadIdx.x;
    for (int i = tid; i < HH * GH3; i += NT) sU[i] = U[i];
    for (int i = tid; i < 2 * GH3; i += NT) sB[i] = bias[i];
    for (int i = tid; i < G * HH; i += NT) sHT[i] = 0.0f;

    const int b0 = blockIdx.x * G;
    const int half = tid / 192;        // warp-uniform (192 = 6 warps)
    const int j    = tid - half * 192; // gate column 0..191

    // stage step-0 table rows (float4 gathers; 768B rows are 16B aligned)
    {
        const int s0 = BWD ? SS - 1 : 0;
        for (int i = tid; i < G * 48; i += NT) {  // exactly 2 iters
            int g = i / 48, q = i - g * 48;
            int id = src_ids[(b0 + g) * SS + s0];
            ((float4*)sXT)[g * 48 + q] = ((const float4*)(TW + id * GH3))[q];
        }
    }
    __syncthreads();

    int cur = 0;
    for (int step = 0; step < SS; ++step) {
        const int s  = BWD ? (SS - 1 - step) : step;
        const int sn = BWD ? (s - 1) : (s + 1);
        float* Xc = &sXT[cur * (G * GH3)];
        float* Xn = &sXT[(cur ^ 1) * (G * GH3)];

        // prefetch next-step table rows into registers (hidden under GEMV)
        float4 pf[2];
        if (step + 1 < SS) {
            int n = 0;
            for (int i = tid; i < G * 48; i += NT) {
                int g = i / 48, q = i - g * 48;
                int id = __ldg(&src_ids[(b0 + g) * SS + sn]);
                pf[n++] = __ldg((const float4*)(TW + id * GH3) + q);
            }
        }

        // h @ U, k-split: this thread covers k in [half*32, half*32+32)
        unsigned long long hp2[8];
        {
            unsigned long long bh = (half == 0) ? pack2(sB[GH3 + j]) : 0ULL;
            #pragma unroll
            for (int p = 0; p < 8; ++p) hp2[p] = bh;
        }
        const int ku0 = half * 32;
        #pragma unroll 4
        for (int kk = 0; kk < 32; ++kk) {
            int k = ku0 + kk;
            unsigned long long u2 = pack2(sU[k * GH3 + j]);
            const ulonglong2* hr = (const ulonglong2*)&sHT[k * G];
            ulonglong2 h0 = hr[0], h1 = hr[1], h2 = hr[2], h3 = hr[3];
            fma2(hp2[0], u2, h0.x); fma2(hp2[1], u2, h0.y);
            fma2(hp2[2], u2, h1.x); fma2(hp2[3], u2, h1.y);
            fma2(hp2[4], u2, h2.x); fma2(hp2[5], u2, h2.y);
            fma2(hp2[6], u2, h3.x); fma2(hp2[7], u2, h3.y);
        }
        #pragma unroll
        for (int p = 0; p < 8; ++p) {
            float lo, hi;
            unpack2(hp2[p], lo, hi);
            sHP[(half * G + 2 * p) * GH3 + j] = lo;
            sHP[(half * G + 2 * p + 1) * GH3 + j] = hi;
        }
        // commit prefetched table rows
        if (step + 1 < SS) {
            int n = 0;
            for (int i = tid; i < G * 48; i += NT) {
                int g = i / 48, q = i - g * 48;
                ((float4*)Xn)[g * 48 + q] = pf[n++];
            }
        }
        __syncthreads();

        // gates (1024 tasks over 384 threads); xp comes straight from table row
        for (int idx = tid; idx < G * HH; idx += NT) {
            int g  = idx >> 6;
            int jj = idx & 63;
            const float* XP  = &Xc[g * GH3];
            const float* HP0 = &sHP[g * GH3];
            const float* HP1 = &sHP[(G + g) * GH3];
            float hz = HP0[jj] + HP1[jj];
            float hr_ = HP0[HH + jj] + HP1[HH + jj];
            float hh = HP0[2 * HH + jj] + HP1[2 * HH + jj];
            float z = fsigmoid(XP[jj] + hz);
            float r = fsigmoid(XP[HH + jj] + hr_);
            float n = ftanh(XP[2 * HH + jj] + r * hh);
            float hold = sHT[jj * G + g];
            float hn = z * hold + (1.0f - z) * n;
            sHT[jj * G + g] = hn;
            dst[(b0 + g) * SS * HH + s * HH + jj] = hn;
        }
        __syncthreads();
        cur ^= 1;
    }
}

// =================================================================
// encoded = fwd + bwd (fused); enc_proj = encoded @ attn_We + be
// =================================================================
__global__ __launch_bounds__(256)
void proj_kernel(const float* __restrict__ We, const float* __restrict__ be)
{
    extern __shared__ float sm[];
    float* sWe = sm;              // 64*64
    float* sbe = sWe + HH * AA;   // 64
    float* sR  = sbe + 64;        // 64 rows * 64

    const int tid = threadIdx.x;
    for (int i = tid; i < HH * AA; i += 256) sWe[i] = We[i];
    if (tid < 64) sbe[tid] = be[tid];
    const int rbase = blockIdx.x * 64;
    for (int i = tid; i < 64 * HH; i += 256) {
        float e = g_fwd[rbase * HH + i] + g_bwd[rbase * HH + i];
        sR[i] = e;
        g_enc[rbase * HH + i] = e;
    }
    __syncthreads();

    const int a  = tid & 63;
    const int rq = tid >> 6;
    float acc[16];
    #pragma unroll
    for (int r = 0; r < 16; ++r) acc[r] = sbe[a];
    for (int k = 0; k < HH; ++k) {
        float w = sWe[k * AA + a];
        #pragma unroll
        for (int r = 0; r < 16; ++r) acc[r] += w * sR[(rq * 16 + r) * HH + k];
    }
    #pragma unroll
    for (int r = 0; r < 16; ++r)
        g_encproj[(rbase + rq * 16 + r) * AA + a] = acc[r];
}

// =================================================================
// Decoder: Bahdanau attention + GRU. G=8 batch/block, 384 threads.
// x-half of dec_W folded into g_TD table (gather per step); loop keeps
// ctx @ dec_W[64:128] + h @ dec_U (k-split f32x2) + attention.
// =================================================================
__global__ __launch_bounds__(384)
void dec_kernel(const int* __restrict__ tgt_ids,
                const float* __restrict__ dW, const float* __restrict__ dU,
                const float* __restrict__ db,
                const float* __restrict__ Wd, const float* __restrict__ bd,
                const float* __restrict__ av, const float* __restrict__ bv)
{
    constexpr int G = 8;
    constexpr int NT = 384;
    constexpr int EPL = AA + 1;  // 65
    extern __shared__ float sm[];
    float* sWc  = sm;                  // ctx half: dec_W rows 64..127 -> 64*192 = 12288
    float* sU   = sWc + HH * GH3;      // 12288
    float* sB   = sU + HH * GH3;       // 384
    float* sWd  = sB + 2 * GH3;        // 4096
    float* sbd  = sWd + HH * AA;       // 64
    float* sv   = sbd + AA;            // 64
    float* sEP  = sv + AA;             // 8*32*65 = 16640
    float* sXPx = sEP + G * SS * EPL;  // 8*192 = 1536 (gathered TD rows, [g][192])
    float* sCtxT= sXPx + G * GH3;      // 64*8 = 512 ([h][g])
    float* sXPc = sCtxT + HH * G;      // 2*8*192 = 3072
    float* sHP  = sXPc + 2 * G * GH3;  // 3072
    float* sHT  = sHP + 2 * G * GH3;   // 512 ([h][g])
    float* sDP  = sHT + HH * G;        // 512
    float* sLg  = sDP + G * AA;        // 256
    float* sInv = sLg + G * SS;        // 8

    const int tid = threadIdx.x;
    const int b0 = blockIdx.x * G;
    const int half = tid / 192;
    const int j    = tid - half * 192;

    for (int i = tid; i < HH * GH3; i += NT) sWc[i] = dW[HH * GH3 + i]; // rows 64..127
    for (int i = tid; i < HH * GH3; i += NT) sU[i] = dU[i];
    for (int i = tid; i < 2 * GH3; i += NT) sB[i] = db[i];
    for (int i = tid; i < HH * AA; i += NT) sWd[i] = Wd[i];
    if (tid < AA) { sbd[tid] = bd[tid]; sv[tid] = av[tid]; }
    const float bvv = bv[0];

    for (int i = tid; i < G * SS * AA; i += NT) {
        int g = i / (SS * AA);
        int rem = i - g * SS * AA;
        int s = rem >> 6;
        int a = rem & 63;
        sEP[g * SS * EPL + s * EPL + a] = g_encproj[(b0 + g) * SS * AA + rem];
    }
    for (int i = tid; i < G * HH; i += NT) {
        int g = i >> 6; int jj = i & 63;
        sHT[jj * G + g] = g_enc[(b0 + g) * SS * HH + jj];
    }
    __syncthreads();

    for (int t = 0; t < TT; ++t) {
        // issue TD gather first (exactly one float4 per thread: 8*48 = 384)
        float4 gx;
        {
            int g = tid / 48, q = tid - (tid / 48) * 48;
            int id = (t == 0) ? 1 : __ldg(&tgt_ids[(b0 + g) * TT + (t - 1)]);
            gx = __ldg((const float4*)(g_TD + id * GH3) + q);
        }
        // dproj = h @ Wd + bd (512 tasks; gather latency hides under this)
        for (int idx = tid; idx < G * AA; idx += NT) {
            int g = idx >> 6; int a = idx & 63;
            float acc = sbd[a];
            #pragma unroll 8
            for (int h = 0; h < HH; ++h) acc += sHT[h * G + g] * sWd[h * AA + a];
            sDP[g * AA + a] = acc;
        }
        {
            ((float4*)sXPx)[tid] = gx;
        }
        __syncthreads();

        // attention scores (256 tasks)
        if (tid < G * SS) {
            int g = tid >> 5; int s = tid & 31;
            const float* ep = &sEP[g * SS * EPL + s * EPL];
            const float* dp = &sDP[g * AA];
            float acc = bvv;
            #pragma unroll 8
            for (int a = 0; a < AA; ++a) acc += sv[a] * tanha(dp[a] + ep[a]);
            sLg[g * SS + s] = acc;
        }
        __syncthreads();

        // softmax over S: one warp per batch element (8 warps)
        if (tid < G * 32) {
            int g = tid >> 5, lane = tid & 31;
            float x = sLg[g * SS + lane];
            float m = x;
            #pragma unroll
            for (int off = 16; off > 0; off >>= 1)
                m = fmaxf(m, __shfl_xor_sync(0xffffffffu, m, off));
            float e = __expf(x - m);
            float sum = e;
            #pragma unroll
            for (int off = 16; off > 0; off >>= 1)
                sum += __shfl_xor_sync(0xffffffffu, sum, off);
            sLg[g * SS + lane] = e;
            if (lane == 0) sInv[g] = __fdividef(1.0f, sum);
        }
        __syncthreads();

        // context -> sCtxT [h][g] (512 tasks)
        for (int idx = tid; idx < G * HH; idx += NT) {
            int g = idx >> 6; int h = idx & 63;
            const float* encb = &g_enc[(b0 + g) * SS * HH];
            float acc = 0.0f;
            #pragma unroll
            for (int s = 0; s < SS; ++s) acc += sLg[g * SS + s] * __ldg(&encb[s * HH + h]);
            sCtxT[h * G + g] = acc * sInv[g];
        }
        __syncthreads();

        // GEMVs (f32x2, k-split): xpc = ctx @ Wc, hp = h @ U
        unsigned long long xc2[4], hp2[4];
        {
            unsigned long long bh = (half == 0) ? pack2(sB[GH3 + j]) : 0ULL;
            #pragma unroll
            for (int p = 0; p < 4; ++p) { xc2[p] = 0ULL; hp2[p] = bh; }
        }
        const int k0 = half * 32;
        #pragma unroll 4
        for (int kk = 0; kk < 32; ++kk) {
            int k = k0 + kk;
            unsigned long long w2 = pack2(sWc[k * GH3 + j]);
            const ulonglong2* cr = (const ulonglong2*)&sCtxT[k * G];
            ulonglong2 c0 = cr[0], c1 = cr[1];
            fma2(xc2[0], w2, c0.x); fma2(xc2[1], w2, c0.y);
            fma2(xc2[2], w2, c1.x); fma2(xc2[3], w2, c1.y);
            unsigned long long u2 = pack2(sU[k * GH3 + j]);
            const ulonglong2* hr = (const ulonglong2*)&sHT[k * G];
            ulonglong2 h0 = hr[0], h1 = hr[1];
            fma2(hp2[0], u2, h0.x); fma2(hp2[1], u2, h0.y);
            fma2(hp2[2], u2, h1.x); fma2(hp2[3], u2, h1.y);
        }
        #pragma unroll
        for (int p = 0; p < 4; ++p) {
            float lo, hi;
            unpack2(xc2[p], lo, hi);
            sXPc[(half * G + 2 * p) * GH3 + j] = lo;
            sXPc[(half * G + 2 * p + 1) * GH3 + j] = hi;
            unpack2(hp2[p], lo, hi);
            sHP[(half * G + 2 * p) * GH3 + j] = lo;
            sHP[(half * G + 2 * p + 1) * GH3 + j] = hi;
        }
        __syncthreads();

        // gates (512 tasks): xz = TD row + ctx-proj halves; hp halves
        for (int idx = tid; idx < G * HH; idx += NT) {
            int g  = idx >> 6;
            int jj = idx & 63;
            const float* XPx = &sXPx[g * GH3];
            const float* XC0 = &sXPc[g * GH3];
            const float* XC1 = &sXPc[(G + g) * GH3];
            const float* HP0 = &sHP[g * GH3];
            const float* HP1 = &sHP[(G + g) * GH3];
            float xz = XPx[jj] + XC0[jj] + XC1[jj];
            float xr = XPx[HH + jj] + XC0[HH + jj] + XC1[HH + jj];
            float xh = XPx[2*HH + jj] + XC0[2*HH + jj] + XC1[2*HH + jj];
            float hz = HP0[jj] + HP1[jj];
            float hr_ = HP0[HH + jj] + HP1[HH + jj];
            float hh = HP0[2*HH + jj] + HP1[2*HH + jj];
            float z = fsigmoid(xz + hz);
            float r = fsigmoid(xr + hr_);
            float n = ftanh(xh + r * hh);
            float hold = sHT[jj * G + g];
            float hn = z * hold + (1.0f - z) * n;
            sHT[jj * G + g] = hn;
            g_hid[(b0 + g) * TT * HH + t * HH + jj] = hn;
        }
        __syncthreads();
    }
}

// =================================================================
// logits = hidden @ out_W + out_b (transposed tile + f32x2; R10 version)
// =================================================================
__global__ __launch_bounds__(256)
void out_kernel(const float* __restrict__ outW, const float* __restrict__ outb,
                float* __restrict__ out)
{
    constexpr int R = 32;
    constexpr int TIL = 4;
    constexpr int PIT = 36;
    extern __shared__ float sm[];
    float* sOW = sm;              // 64*256
    float* sOB = sOW + HH * VOC;  // 256
    float* sRT = sOB + VOC;       // 64 * 36

    const int tid = threadIdx.x;
    for (int i = tid; i < HH * VOC; i += 256) sOW[i] = outW[i];
    sOB[tid] = outb[tid];

    for (int tile = 0; tile < TIL; ++tile) {
        const int rbase = (blockIdx.x * TIL + tile) * R;
        __syncthreads();
        for (int i = tid; i < R * HH; i += 256) {
            int r = i >> 6, k = i & 63;
            sRT[k * PIT + r] = g_hid[(rbase + r) * HH + k];
        }
        __syncthreads();

        const int v = tid;
        const unsigned long long b2 = pack2(sOB[v]);
        unsigned long long acc2[16];
        #pragma unroll
        for (int p = 0; p < 16; ++p) acc2[p] = b2;

        #pragma unroll 4
        for (int k = 0; k < HH; ++k) {
            unsigned long long w2 = pack2(sOW[k * VOC + v]);
            const ulonglong2* row = (const ulonglong2*)&sRT[k * PIT];
            #pragma unroll
            for (int q = 0; q < 8; ++q) {
                ulonglong2 rp = row[q];
                fma2(acc2[2 * q], w2, rp.x);
                fma2(acc2[2 * q + 1], w2, rp.y);
            }
        }
        #pragma unroll
        for (int p = 0; p < 16; ++p) {
            float lo, hi;
            unpack2(acc2[p], lo, hi);
            out[(rbase + 2 * p) * VOC + v] = lo;
            out[(rbase + 2 * p + 1) * VOC + v] = hi;
        }
    }
}

// =================================================================
// launch
// =================================================================
extern "C" void kernel_launch(void* const* d_in, const int* in_sizes, int n_in,
                              void* d_out, int out_size)
{
    const int* src_ids = (const int*)d_in[0];   // int32 (JAX x64 disabled)
    const int* tgt_ids = (const int*)d_in[1];   // int32
    const float* src_emb = (const float*)d_in[2];
    const float* enc_Wf  = (const float*)d_in[3];
    const float* enc_Uf  = (const float*)d_in[4];
    const float* enc_bf  = (const float*)d_in[5];
    const float* enc_Wb  = (const float*)d_in[6];
    const float* enc_Ub  = (const float*)d_in[7];
    const float* enc_bb  = (const float*)d_in[8];
    const float* attn_We = (const float*)d_in[9];
    const float* attn_be = (const float*)d_in[10];
    const float* attn_Wd = (const float*)d_in[11];
    const float* attn_bd = (const float*)d_in[12];
    const float* attn_v  = (const float*)d_in[13];
    const float* attn_bv = (const float*)d_in[14];
    const float* dec_W   = (const float*)d_in[15];
    const float* dec_U   = (const float*)d_in[16];
    const float* dec_b   = (const float*)d_in[17];
    const float* out_W   = (const float*)d_in[18];
    const float* out_b   = (const float*)d_in[19];
    float* out = (float*)d_out;

    const int ENC_SMEM  = (12288 + 384 + 6144 + 1024 + 6144) * 4;                // 103936
    const int PROJ_SMEM = (4096 + 64 + 4096) * 4;                                 // 33024
    const int DEC_SMEM  = (12288 + 12288 + 384 + 4096 + 64 + 64 + 16640 + 1536
                           + 512 + 3072 + 3072 + 512 + 512 + 256 + 8) * 4;        // 221216
    const int OUT_SMEM  = (16384 + 256 + 64 * 36) * 4;                            // 75776

    cudaFuncSetAttribute(enc_kernel, cudaFuncAttributeMaxDynamicSharedMemorySize, ENC_SMEM);
    cudaFuncSetAttribute(dec_kernel, cudaFuncAttributeMaxDynamicSharedMemorySize, DEC_SMEM);
    cudaFuncSetAttribute(out_kernel, cudaFuncAttributeMaxDynamicSharedMemorySize, OUT_SMEM);

    table_kernel<<<VOC, 192>>>(src_emb, enc_Wf, enc_bf, enc_Wb, enc_bb,
                               dec_W, dec_b, out_W);
    dim3 enc_grid(BB / 16, 2);
    enc_kernel<<<enc_grid, 384, ENC_SMEM>>>(src_ids, enc_Uf, enc_bf, enc_Ub, enc_bb);
    proj_kernel<<<(BB * SS) / 64, 256, PROJ_SMEM>>>(attn_We, attn_be);
    dec_kernel<<<BB / 8, 384, DEC_SMEM>>>(tgt_ids, dec_W, dec_U, dec_b,
                                          attn_Wd, attn_bd, attn_v, attn_bv);
    out_kernel<<<(BB * TT) / (32 * 4), 256, OUT_SMEM>>>(out_W, out_b, out);
}